// round 14
// baseline (speedup 1.0000x reference)
#include <cuda_runtime.h>
#include <cuda_fp16.h>
#include <math_constants.h>
#include <cstdint>

// FixedMoiraiGating: logits = x @ W^T + b ; top-2 ; softmax over the 2 vals.
// x: [8192, 4096] f32, W: [64, 4096] f32, b: [64] f32
// out f32[32768]: [0,16384) = probs; [16384,32768) = indices as float.
//
// R14 = R13 resubmit (infra flake): 2-term GEMM  logits' = (xh + xl) @ wh^T
// (exact in x; W fp16-rounded, logit err sigma ~1e-4), A-prefetch ring depth
// 4 (covers DRAM latency at 2-term MMA pace). Phase 2: top-3 + flag tokens
// with decision gap < 1e-3. Phase 3: for flagged tokens, recompute EXACT fp32
// logits only for experts within 1.5e-3 of approx v2, fix outputs.

#define D_DIM  4096
#define E_DIM  64
#define BM     128
#define KHALF  2048
#define KGRP   1024
#define KC     64
#define NSG    (KGRP / KC)    // 16 stages/group
#define NKG    (KGRP / 16)    // 64 ksteps/group
#define NTOK   8192
#define TH_FLAG 1e-3f
#define TH_BAND 1.5e-3f

// smem: group g: Bh double-buffer 2x8KB
#define BH(g, d)   ((g) * 16384 + (d) * 8192)
#define SMEM_ALLOC (32768 + 1024)

__device__ float g_scratch[2 * NTOK * E_DIM];
__device__ int   g_cnt;
__device__ int   g_flags[NTOK];

#define MMA16816(c, a0, a1, a2, a3, b0, b1) \
    asm volatile("mma.sync.aligned.m16n8k16.row.col.f32.f16.f16.f32 " \
                 "{%0,%1,%2,%3}, {%4,%5,%6,%7}, {%8,%9}, {%0,%1,%2,%3};" \
                 : "+f"((c)[0]), "+f"((c)[1]), "+f"((c)[2]), "+f"((c)[3]) \
                 : "r"(a0), "r"(a1), "r"(a2), "r"(a3), "r"(b0), "r"(b1))

#define LDSM_X4(r0, r1, r2, r3, addr) \
    asm volatile("ldmatrix.sync.aligned.m8n8.x4.shared.b16 {%0,%1,%2,%3}, [%4];" \
                 : "=r"(r0), "=r"(r1), "=r"(r2), "=r"(r3) : "r"(addr))

static __device__ __forceinline__ uint32_t smem_u32(const void* p) {
    uint32_t a;
    asm("{ .reg .u64 t; cvta.to.shared.u64 t, %1; cvt.u32.u64 %0, t; }"
        : "=r"(a) : "l"(p));
    return a;
}

static __device__ __forceinline__ uint32_t h2u(__half2 h) {
    return *reinterpret_cast<uint32_t*>(&h);
}

static __device__ __forceinline__ void split2(float2 v, uint32_t& hi, uint32_t& lo) {
    __half2 h = __floats2half2_rn(v.x, v.y);
    float2 bk = __half22float2(h);
    __half2 l = __floats2half2_rn(v.x - bk.x, v.y - bk.y);
    hi = h2u(h);
    lo = h2u(l);
}

static __device__ __forceinline__ uint32_t bswz(int n, uint32_t kbyte) {
    return (uint32_t)(n * 128) + (kbyte ^ (uint32_t)((n & 7) << 4));
}

// ---- Phase 1: 2-term GEMM, A-ring-4, intra-CTA split-K, grid split-K=2 ----
__global__ __launch_bounds__(512, 1)
void moirai_gemm_kernel(const float* __restrict__ x,
                        const float* __restrict__ W)
{
    extern __shared__ uint8_t smem_raw[];
    const uint32_t base = (smem_u32(smem_raw) + 1023u) & ~1023u;

    if (blockIdx.x == 0 && threadIdx.x == 0) g_cnt = 0;

    const int t    = threadIdx.x;
    const int w    = t >> 5;
    const int lane = t & 31;
    const int gi   = w >> 3;
    const int wg   = w & 7;
    const int tg   = t & 255;
    const int tq   = lane >> 2;
    const int tr   = lane & 3;
    const int mt   = blockIdx.x & 63;
    const int kh   = blockIdx.x >> 6;
    const int tok0 = mt * BM;
    const int kbg  = kh * KHALF + gi * KGRP;

    const uint32_t bh0 = base + BH(gi, 0);
    const uint32_t bh1 = base + BH(gi, 1);

    const int t7 = lane & 7;
    const int j  = lane >> 3;
    const int jp = j & 1;
    const int jh = j >> 1;
    const uint32_t lanePart = (uint32_t)(jh * 1024 + t7 * 128);
    const uint32_t xorTerm  = (uint32_t)(t7 << 4);

    float acc[8][4];
#pragma unroll
    for (int nt = 0; nt < 8; nt++)
#pragma unroll
        for (int c = 0; c < 4; c++) acc[nt][c] = 0.0f;

    const int rA = tok0 + wg * 16 + tq;

    float2 af[4][4];        // A prefetch ring, depth 4 ksteps
#define LOAD_A(slot, g) do {                                            \
        int kc_ = kbg + (g) * 16 + 2 * tr;                              \
        const float* p0_ = x + (size_t)rA * D_DIM + kc_;                \
        const float* p1_ = x + (size_t)(rA + 8) * D_DIM + kc_;          \
        af[slot][0] = *reinterpret_cast<const float2*>(p0_);            \
        af[slot][1] = *reinterpret_cast<const float2*>(p0_ + 8);        \
        af[slot][2] = *reinterpret_cast<const float2*>(p1_);            \
        af[slot][3] = *reinterpret_cast<const float2*>(p1_ + 8);        \
    } while (0)

    float4 bf4[4];
    int   brow[4], bc4[4];
#pragma unroll
    for (int i = 0; i < 4; i++) {
        int p = tg + i * 256;
        brow[i] = p >> 4;
        bc4[i]  = p & 15;
    }

#pragma unroll
    for (int i = 0; i < 4; i++)
        bf4[i] = *reinterpret_cast<const float4*>(
            W + (size_t)brow[i] * D_DIM + kbg + bc4[i] * 4);
    LOAD_A(0, 0);
    LOAD_A(1, 1);
    LOAD_A(2, 2);
    LOAD_A(3, 3);
#pragma unroll
    for (int i = 0; i < 4; i++) {
        __half2 h0 = __floats2half2_rn(bf4[i].x, bf4[i].y);
        __half2 h1 = __floats2half2_rn(bf4[i].z, bf4[i].w);
        uint32_t off = bswz(brow[i], (uint32_t)(bc4[i] * 8));
        asm volatile("st.shared.v2.b32 [%0], {%1,%2};" :: "r"(bh0 + off),
                     "r"(h2u(h0)), "r"(h2u(h1)) : "memory");
    }
    __syncthreads();

    for (int stage = 0; stage < NSG; stage++) {
        const uint32_t curh = (stage & 1) ? bh1 : bh0;
        const uint32_t nxth = (stage & 1) ? bh0 : bh1;

        if (stage + 1 < NSG) {
            const int kbs = kbg + (stage + 1) * KC;
#pragma unroll
            for (int i = 0; i < 4; i++)
                bf4[i] = *reinterpret_cast<const float4*>(
                    W + (size_t)brow[i] * D_DIM + kbs + bc4[i] * 4);
        }

#pragma unroll
        for (int ks = 0; ks < 4; ks++) {
            const int g = stage * 4 + ks;
            const int slot = g & 3;

            uint32_t bhf[8][2];
            const uint32_t kpart = ((uint32_t)(ks << 5) | (uint32_t)(jp << 4)) ^ xorTerm;
#pragma unroll
            for (int q = 0; q < 8; q += 2) {
                uint32_t ah_ = curh + (uint32_t)(q * 1024) + lanePart + kpart;
                LDSM_X4(bhf[q][0], bhf[q][1], bhf[q + 1][0], bhf[q + 1][1], ah_);
            }

            uint32_t ah[4], al[4];
#pragma unroll
            for (int jj = 0; jj < 4; jj++)
                split2(af[slot][jj], ah[jj], al[jj]);

            if (g + 4 < NKG) LOAD_A(slot, g + 4);

#pragma unroll
            for (int nt = 0; nt < 8; nt++) {
                MMA16816(acc[nt], ah[0], ah[2], ah[1], ah[3], bhf[nt][0], bhf[nt][1]);
                MMA16816(acc[nt], al[0], al[2], al[1], al[3], bhf[nt][0], bhf[nt][1]);
            }
        }

        if (stage + 1 < NSG) {
#pragma unroll
            for (int i = 0; i < 4; i++) {
                __half2 h0 = __floats2half2_rn(bf4[i].x, bf4[i].y);
                __half2 h1 = __floats2half2_rn(bf4[i].z, bf4[i].w);
                uint32_t off = bswz(brow[i], (uint32_t)(bc4[i] * 8));
                asm volatile("st.shared.v2.b32 [%0], {%1,%2};" :: "r"(nxth + off),
                             "r"(h2u(h0)), "r"(h2u(h1)) : "memory");
            }
        }
        __syncthreads();
    }

    // combine the two K-groups
    if (gi == 1) {
        uint32_t dst = base + (uint32_t)(wg * 4096 + lane * 128);
#pragma unroll
        for (int nt = 0; nt < 8; nt++) {
            asm volatile("st.shared.v4.b32 [%0], {%1,%2,%3,%4};" ::
                         "r"(dst + nt * 16),
                         "f"(acc[nt][0]), "f"(acc[nt][1]),
                         "f"(acc[nt][2]), "f"(acc[nt][3]) : "memory");
        }
    }
    __syncthreads();

    if (gi == 0) {
        uint32_t src = base + (uint32_t)(wg * 4096 + lane * 128);
#pragma unroll
        for (int nt = 0; nt < 8; nt++) {
            float r0, r1, r2, r3;
            asm volatile("ld.shared.v4.b32 {%0,%1,%2,%3}, [%4];"
                         : "=f"(r0), "=f"(r1), "=f"(r2), "=f"(r3)
                         : "r"(src + nt * 16));
            acc[nt][0] += r0; acc[nt][1] += r1;
            acc[nt][2] += r2; acc[nt][3] += r3;
        }
        float* sbase = g_scratch + (size_t)kh * NTOK * E_DIM;
#pragma unroll
        for (int nt = 0; nt < 8; nt++) {
            int col = nt * 8 + 2 * tr;
            *reinterpret_cast<float2*>(sbase + (size_t)rA * E_DIM + col) =
                make_float2(acc[nt][0], acc[nt][1]);
            *reinterpret_cast<float2*>(sbase + (size_t)(rA + 8) * E_DIM + col) =
                make_float2(acc[nt][2], acc[nt][3]);
        }
    }
}

// ---- Phase 2: combine halves + bias, top-3, flag ambiguous, provisional out ----
__global__ __launch_bounds__(256, 4)
void moirai_topk_kernel(const float* __restrict__ b,
                        float* __restrict__ out)
{
    const int gid  = blockIdx.x * 256 + threadIdx.x;
    const int tok  = gid >> 1;
    const int hf   = gid & 1;

    const float* r0 = g_scratch + (size_t)tok * E_DIM + hf * 32;
    const float* r1 = g_scratch + ((size_t)NTOK + tok) * E_DIM + hf * 32;
    const float* bb = b + hf * 32;

    float v1 = -CUDART_INF_F, v2 = -CUDART_INF_F, v3 = -CUDART_INF_F;
    int i1 = 0, i2 = 0;
#pragma unroll
    for (int g = 0; g < 8; g++) {
        float4 a  = *reinterpret_cast<const float4*>(r0 + g * 4);
        float4 c  = *reinterpret_cast<const float4*>(r1 + g * 4);
        float4 bv = *reinterpret_cast<const float4*>(bb + g * 4);
        float v[4] = {a.x + c.x + bv.x, a.y + c.y + bv.y,
                      a.z + c.z + bv.z, a.w + c.w + bv.w};
#pragma unroll
        for (int jj = 0; jj < 4; jj++) {
            int e = hf * 32 + g * 4 + jj;
            if (v[jj] > v1)      { v3 = v2; v2 = v1; i2 = i1; v1 = v[jj]; i1 = e; }
            else if (v[jj] > v2) { v3 = v2; v2 = v[jj]; i2 = e; }
            else if (v[jj] > v3) { v3 = v[jj]; }
        }
    }

    {
        float V1 = __shfl_xor_sync(0xFFFFFFFFu, v1, 1);
        float V2 = __shfl_xor_sync(0xFFFFFFFFu, v2, 1);
        float V3 = __shfl_xor_sync(0xFFFFFFFFu, v3, 1);
        int   I1 = __shfl_xor_sync(0xFFFFFFFFu, i1, 1);
        int   I2 = __shfl_xor_sync(0xFFFFFFFFu, i2, 1);

        if (V1 > v1 || (V1 == v1 && I1 < i1)) {
            float tv; int ti;
            tv = v1; v1 = V1; V1 = tv;  ti = i1; i1 = I1; I1 = ti;
            tv = v2; v2 = V2; V2 = tv;  ti = i2; i2 = I2; I2 = ti;
            tv = v3; v3 = V3; V3 = tv;
        }
        if (V1 > v2 || (V1 == v2 && I1 < i2)) {
            v3 = fmaxf(v2, V2);
            v2 = V1; i2 = I1;
        } else {
            v3 = fmaxf(v3, V1);
        }
    }

    if (hf == 0) {
        if ((v1 - v2 < TH_FLAG) || (v2 - v3 < TH_FLAG)) {
            int idx = atomicAdd(&g_cnt, 1);
            if (idx < NTOK) g_flags[idx] = tok;
        }
        float ex  = expf(v2 - v1);
        float inv = 1.0f / (1.0f + ex);
        out[tok * 2 + 0] = inv;
        out[tok * 2 + 1] = ex * inv;
        float* idx_out = out + (size_t)NTOK * 2;
        idx_out[tok * 2 + 0] = (float)i1;
        idx_out[tok * 2 + 1] = (float)i2;
    }
}

// ---- Phase 3: exact rescue of flagged tokens, band candidates only ----
__global__ __launch_bounds__(256, 2)
void moirai_rescue_kernel(const float* __restrict__ x,
                          const float* __restrict__ W,
                          const float* __restrict__ b,
                          float* __restrict__ out)
{
    __shared__ float s_log[E_DIM];
    __shared__ int   s_cand[E_DIM];
    __shared__ int   s_n;
    __shared__ float s_part[8];
    __shared__ float s_exact[E_DIM];

    const int tid = threadIdx.x;
    const int cnt = min(g_cnt, NTOK);

    for (int i = blockIdx.x; i < cnt; i += gridDim.x) {
        const int tok = g_flags[i];

        if (tid < E_DIM)
            s_log[tid] = g_scratch[(size_t)tok * E_DIM + tid]
                       + g_scratch[(size_t)(NTOK + tok) * E_DIM + tid] + b[tid];
        __syncthreads();

        if (tid == 0) {
            float v1 = -CUDART_INF_F, v2 = -CUDART_INF_F;
            for (int e = 0; e < E_DIM; e++) {
                float v = s_log[e];
                if (v > v1)      { v2 = v1; v1 = v; }
                else if (v > v2) { v2 = v; }
            }
            float band = v2 - TH_BAND;
            int n = 0;
            for (int e = 0; e < E_DIM; e++)
                if (s_log[e] >= band) s_cand[n++] = e;
            s_n = n;
        }
        __syncthreads();
        const int n = s_n;

        for (int c = 0; c < n; c++) {
            const int e = s_cand[c];
            const float* xr = x + (size_t)tok * D_DIM + tid * 16;
            const float* wr = W + (size_t)e * D_DIM + tid * 16;
            float s = 0.0f;
#pragma unroll
            for (int k = 0; k < 16; k += 4) {
                float4 a  = *reinterpret_cast<const float4*>(xr + k);
                float4 ww = *reinterpret_cast<const float4*>(wr + k);
                s += a.x * ww.x + a.y * ww.y + a.z * ww.z + a.w * ww.w;
            }
#pragma unroll
            for (int m = 16; m; m >>= 1) s += __shfl_xor_sync(0xFFFFFFFFu, s, m);
            if ((tid & 31) == 0) s_part[tid >> 5] = s;
            __syncthreads();
            if (tid == 0) {
                float tot = 0.0f;
#pragma unroll
                for (int ww = 0; ww < 8; ww++) tot += s_part[ww];
                s_exact[c] = tot + b[e];
            }
            __syncthreads();
        }

        if (tid == 0) {
            float v1 = -CUDART_INF_F, v2 = -CUDART_INF_F;
            int i1 = 0, i2 = 0;
            for (int c = 0; c < n; c++) {       // s_cand ascending -> tie: lower e wins
                int e = s_cand[c];
                float v = s_exact[c];
                if (v > v1)      { v2 = v1; i2 = i1; v1 = v; i1 = e; }
                else if (v > v2) { v2 = v; i2 = e; }
            }
            float ex  = expf(v2 - v1);
            float inv = 1.0f / (1.0f + ex);
            out[tok * 2 + 0] = inv;
            out[tok * 2 + 1] = ex * inv;
            float* idx_out = out + (size_t)NTOK * 2;
            idx_out[tok * 2 + 0] = (float)i1;
            idx_out[tok * 2 + 1] = (float)i2;
        }
        __syncthreads();
    }
}

extern "C" void kernel_launch(void* const* d_in, const int* in_sizes, int n_in,
                              void* d_out, int out_size)
{
    const float* x = (const float*)d_in[0];
    const float* W = (const float*)d_in[1];
    const float* b = (const float*)d_in[2];
    float* out = (float*)d_out;

    cudaFuncSetAttribute(moirai_gemm_kernel,
                         cudaFuncAttributeMaxDynamicSharedMemorySize, SMEM_ALLOC);
    moirai_gemm_kernel<<<128, 512, SMEM_ALLOC>>>(x, W);
    moirai_topk_kernel<<<(NTOK * 2) / 256, 256>>>(b, out);
    moirai_rescue_kernel<<<128, 256>>>(x, W, b, out);
}

// round 15
// speedup vs baseline: 1.0350x; 1.0350x over previous
#include <cuda_runtime.h>
#include <cuda_fp16.h>
#include <math_constants.h>
#include <cstdint>

// FixedMoiraiGating: logits = x @ W^T + b ; top-2 ; softmax over the 2 vals.
// x: [8192, 4096] f32, W: [64, 4096] f32, b: [64] f32
// out f32[32768]: [0,16384) = probs; [16384,32768) = indices as float.
//
// R15: 2-term GEMM (logits' = (xh+xl) @ wh^T) with REGISTER-PIPELINED kstep
// loop: LDSM(ks+1) + convert(g+1) issued before MMA(ks), double-buffered
// fragments. Phase 2: top-3 + flag gap < 1e-3. Phase 3: banded exact rescue.

#define D_DIM  4096
#define E_DIM  64
#define BM     128
#define KHALF  2048
#define KGRP   1024
#define KC     64
#define NSG    (KGRP / KC)    // 16 stages/group
#define NKG    (KGRP / 16)    // 64 ksteps/group
#define NTOK   8192
#define TH_FLAG 1e-3f
#define TH_BAND 1.5e-3f

#define BH(g, d)   ((g) * 16384 + (d) * 8192)
#define SMEM_ALLOC (32768 + 1024)

__device__ float g_scratch[2 * NTOK * E_DIM];
__device__ int   g_cnt;
__device__ int   g_flags[NTOK];

#define MMA16816(c, a0, a1, a2, a3, b0, b1) \
    asm volatile("mma.sync.aligned.m16n8k16.row.col.f32.f16.f16.f32 " \
                 "{%0,%1,%2,%3}, {%4,%5,%6,%7}, {%8,%9}, {%0,%1,%2,%3};" \
                 : "+f"((c)[0]), "+f"((c)[1]), "+f"((c)[2]), "+f"((c)[3]) \
                 : "r"(a0), "r"(a1), "r"(a2), "r"(a3), "r"(b0), "r"(b1))

#define LDSM_X4(r0, r1, r2, r3, addr) \
    asm volatile("ldmatrix.sync.aligned.m8n8.x4.shared.b16 {%0,%1,%2,%3}, [%4];" \
                 : "=r"(r0), "=r"(r1), "=r"(r2), "=r"(r3) : "r"(addr))

static __device__ __forceinline__ uint32_t smem_u32(const void* p) {
    uint32_t a;
    asm("{ .reg .u64 t; cvta.to.shared.u64 t, %1; cvt.u32.u64 %0, t; }"
        : "=r"(a) : "l"(p));
    return a;
}

static __device__ __forceinline__ uint32_t h2u(__half2 h) {
    return *reinterpret_cast<uint32_t*>(&h);
}

static __device__ __forceinline__ void split2(float2 v, uint32_t& hi, uint32_t& lo) {
    __half2 h = __floats2half2_rn(v.x, v.y);
    float2 bk = __half22float2(h);
    __half2 l = __floats2half2_rn(v.x - bk.x, v.y - bk.y);
    hi = h2u(h);
    lo = h2u(l);
}

static __device__ __forceinline__ uint32_t bswz(int n, uint32_t kbyte) {
    return (uint32_t)(n * 128) + (kbyte ^ (uint32_t)((n & 7) << 4));
}

// ---- Phase 1: 2-term GEMM, register-pipelined ksteps ----
__global__ __launch_bounds__(512, 1)
void moirai_gemm_kernel(const float* __restrict__ x,
                        const float* __restrict__ W)
{
    extern __shared__ uint8_t smem_raw[];
    const uint32_t base = (smem_u32(smem_raw) + 1023u) & ~1023u;

    if (blockIdx.x == 0 && threadIdx.x == 0) g_cnt = 0;

    const int t    = threadIdx.x;
    const int w    = t >> 5;
    const int lane = t & 31;
    const int gi   = w >> 3;
    const int wg   = w & 7;
    const int tg   = t & 255;
    const int tq   = lane >> 2;
    const int tr   = lane & 3;
    const int mt   = blockIdx.x & 63;
    const int kh   = blockIdx.x >> 6;
    const int tok0 = mt * BM;
    const int kbg  = kh * KHALF + gi * KGRP;

    const uint32_t bh0 = base + BH(gi, 0);
    const uint32_t bh1 = base + BH(gi, 1);

    const int t7 = lane & 7;
    const int j  = lane >> 3;
    const int jp = j & 1;
    const int jh = j >> 1;
    const uint32_t lanePart = (uint32_t)(jh * 1024 + t7 * 128);
    const uint32_t xorTerm  = (uint32_t)(t7 << 4);

    float acc[8][4];
#pragma unroll
    for (int nt = 0; nt < 8; nt++)
#pragma unroll
        for (int c = 0; c < 4; c++) acc[nt][c] = 0.0f;

    const int rA = tok0 + wg * 16 + tq;

    float2 af[2][4];                 // A f32 ring, depth 2 ksteps
#define LOAD_A(slot, g) do {                                            \
        int kc_ = kbg + (g) * 16 + 2 * tr;                              \
        const float* p0_ = x + (size_t)rA * D_DIM + kc_;                \
        const float* p1_ = x + (size_t)(rA + 8) * D_DIM + kc_;          \
        af[slot][0] = *reinterpret_cast<const float2*>(p0_);            \
        af[slot][1] = *reinterpret_cast<const float2*>(p0_ + 8);        \
        af[slot][2] = *reinterpret_cast<const float2*>(p1_);            \
        af[slot][3] = *reinterpret_cast<const float2*>(p1_ + 8);        \
    } while (0)

    float4 bf4[4];
    int   brow[4], bc4[4];
#pragma unroll
    for (int i = 0; i < 4; i++) {
        int p = tg + i * 256;
        brow[i] = p >> 4;
        bc4[i]  = p & 15;
    }

#pragma unroll
    for (int i = 0; i < 4; i++)
        bf4[i] = *reinterpret_cast<const float4*>(
            W + (size_t)brow[i] * D_DIM + kbg + bc4[i] * 4);
    LOAD_A(0, 0);
    LOAD_A(1, 1);
#pragma unroll
    for (int i = 0; i < 4; i++) {
        __half2 h0 = __floats2half2_rn(bf4[i].x, bf4[i].y);
        __half2 h1 = __floats2half2_rn(bf4[i].z, bf4[i].w);
        uint32_t off = bswz(brow[i], (uint32_t)(bc4[i] * 8));
        asm volatile("st.shared.v2.b32 [%0], {%1,%2};" :: "r"(bh0 + off),
                     "r"(h2u(h0)), "r"(h2u(h1)) : "memory");
    }
    __syncthreads();

    // pipelined fragment sets
    uint32_t bhf[2][8][2];
    uint32_t ah2[2][4], al2[2][4];

#define LDSM_STAGE(set, curh, ks) do {                                          \
        const uint32_t kp_ = ((uint32_t)((ks) << 5) | (uint32_t)(jp << 4)) ^ xorTerm; \
        _Pragma("unroll")                                                       \
        for (int q_ = 0; q_ < 8; q_ += 2) {                                     \
            uint32_t a_ = (curh) + (uint32_t)(q_ * 1024) + lanePart + kp_;      \
            LDSM_X4(bhf[set][q_][0], bhf[set][q_][1],                           \
                    bhf[set][q_ + 1][0], bhf[set][q_ + 1][1], a_);              \
        }                                                                       \
    } while (0)

#define CVT_A(set, g) do {                                                      \
        _Pragma("unroll")                                                       \
        for (int jj_ = 0; jj_ < 4; jj_++)                                       \
            split2(af[(g) & 1][jj_], ah2[set][jj_], al2[set][jj_]);             \
    } while (0)

    for (int stage = 0; stage < NSG; stage++) {
        const uint32_t curh = (stage & 1) ? bh1 : bh0;
        const uint32_t nxth = (stage & 1) ? bh0 : bh1;
        const int g0 = stage * 4;

        if (stage + 1 < NSG) {
            const int kbs = kbg + (stage + 1) * KC;
#pragma unroll
            for (int i = 0; i < 4; i++)
                bf4[i] = *reinterpret_cast<const float4*>(
                    W + (size_t)brow[i] * D_DIM + kbs + bc4[i] * 4);
        }

        // prime kstep 0 of this stage
        LDSM_STAGE(0, curh, 0);
        CVT_A(0, g0);

#pragma unroll
        for (int ks = 0; ks < 4; ks++) {
            const int g = g0 + ks;
            const int set = ks & 1;

            // prefetch next kstep's fragments (hidden under this kstep's MMAs)
            if (ks < 3) {
                LDSM_STAGE(set ^ 1, curh, ks + 1);
                CVT_A(set ^ 1, g + 1);
            }
            if (g + 2 < NKG) LOAD_A(g & 1, g + 2);

#pragma unroll
            for (int nt = 0; nt < 8; nt++) {
                MMA16816(acc[nt], ah2[set][0], ah2[set][2], ah2[set][1], ah2[set][3],
                         bhf[set][nt][0], bhf[set][nt][1]);
                MMA16816(acc[nt], al2[set][0], al2[set][2], al2[set][1], al2[set][3],
                         bhf[set][nt][0], bhf[set][nt][1]);
            }
        }

        if (stage + 1 < NSG) {
#pragma unroll
            for (int i = 0; i < 4; i++) {
                __half2 h0 = __floats2half2_rn(bf4[i].x, bf4[i].y);
                __half2 h1 = __floats2half2_rn(bf4[i].z, bf4[i].w);
                uint32_t off = bswz(brow[i], (uint32_t)(bc4[i] * 8));
                asm volatile("st.shared.v2.b32 [%0], {%1,%2};" :: "r"(nxth + off),
                             "r"(h2u(h0)), "r"(h2u(h1)) : "memory");
            }
        }
        __syncthreads();
    }

    // combine the two K-groups
    if (gi == 1) {
        uint32_t dst = base + (uint32_t)(wg * 4096 + lane * 128);
#pragma unroll
        for (int nt = 0; nt < 8; nt++) {
            asm volatile("st.shared.v4.b32 [%0], {%1,%2,%3,%4};" ::
                         "r"(dst + nt * 16),
                         "f"(acc[nt][0]), "f"(acc[nt][1]),
                         "f"(acc[nt][2]), "f"(acc[nt][3]) : "memory");
        }
    }
    __syncthreads();

    if (gi == 0) {
        uint32_t src = base + (uint32_t)(wg * 4096 + lane * 128);
#pragma unroll
        for (int nt = 0; nt < 8; nt++) {
            float r0, r1, r2, r3;
            asm volatile("ld.shared.v4.b32 {%0,%1,%2,%3}, [%4];"
                         : "=f"(r0), "=f"(r1), "=f"(r2), "=f"(r3)
                         : "r"(src + nt * 16));
            acc[nt][0] += r0; acc[nt][1] += r1;
            acc[nt][2] += r2; acc[nt][3] += r3;
        }
        float* sbase = g_scratch + (size_t)kh * NTOK * E_DIM;
#pragma unroll
        for (int nt = 0; nt < 8; nt++) {
            int col = nt * 8 + 2 * tr;
            *reinterpret_cast<float2*>(sbase + (size_t)rA * E_DIM + col) =
                make_float2(acc[nt][0], acc[nt][1]);
            *reinterpret_cast<float2*>(sbase + (size_t)(rA + 8) * E_DIM + col) =
                make_float2(acc[nt][2], acc[nt][3]);
        }
    }
}

// ---- Phase 2: combine halves + bias, top-3, flag ambiguous, provisional out ----
__global__ __launch_bounds__(256, 4)
void moirai_topk_kernel(const float* __restrict__ b,
                        float* __restrict__ out)
{
    const int gid  = blockIdx.x * 256 + threadIdx.x;
    const int tok  = gid >> 1;
    const int hf   = gid & 1;

    const float* r0 = g_scratch + (size_t)tok * E_DIM + hf * 32;
    const float* r1 = g_scratch + ((size_t)NTOK + tok) * E_DIM + hf * 32;
    const float* bb = b + hf * 32;

    float v1 = -CUDART_INF_F, v2 = -CUDART_INF_F, v3 = -CUDART_INF_F;
    int i1 = 0, i2 = 0;
#pragma unroll
    for (int g = 0; g < 8; g++) {
        float4 a  = *reinterpret_cast<const float4*>(r0 + g * 4);
        float4 c  = *reinterpret_cast<const float4*>(r1 + g * 4);
        float4 bv = *reinterpret_cast<const float4*>(bb + g * 4);
        float v[4] = {a.x + c.x + bv.x, a.y + c.y + bv.y,
                      a.z + c.z + bv.z, a.w + c.w + bv.w};
#pragma unroll
        for (int jj = 0; jj < 4; jj++) {
            int e = hf * 32 + g * 4 + jj;
            if (v[jj] > v1)      { v3 = v2; v2 = v1; i2 = i1; v1 = v[jj]; i1 = e; }
            else if (v[jj] > v2) { v3 = v2; v2 = v[jj]; i2 = e; }
            else if (v[jj] > v3) { v3 = v[jj]; }
        }
    }

    {
        float V1 = __shfl_xor_sync(0xFFFFFFFFu, v1, 1);
        float V2 = __shfl_xor_sync(0xFFFFFFFFu, v2, 1);
        float V3 = __shfl_xor_sync(0xFFFFFFFFu, v3, 1);
        int   I1 = __shfl_xor_sync(0xFFFFFFFFu, i1, 1);
        int   I2 = __shfl_xor_sync(0xFFFFFFFFu, i2, 1);

        if (V1 > v1 || (V1 == v1 && I1 < i1)) {
            float tv; int ti;
            tv = v1; v1 = V1; V1 = tv;  ti = i1; i1 = I1; I1 = ti;
            tv = v2; v2 = V2; V2 = tv;  ti = i2; i2 = I2; I2 = ti;
            tv = v3; v3 = V3; V3 = tv;
        }
        if (V1 > v2 || (V1 == v2 && I1 < i2)) {
            v3 = fmaxf(v2, V2);
            v2 = V1; i2 = I1;
        } else {
            v3 = fmaxf(v3, V1);
        }
    }

    if (hf == 0) {
        if ((v1 - v2 < TH_FLAG) || (v2 - v3 < TH_FLAG)) {
            int idx = atomicAdd(&g_cnt, 1);
            if (idx < NTOK) g_flags[idx] = tok;
        }
        float ex  = expf(v2 - v1);
        float inv = 1.0f / (1.0f + ex);
        out[tok * 2 + 0] = inv;
        out[tok * 2 + 1] = ex * inv;
        float* idx_out = out + (size_t)NTOK * 2;
        idx_out[tok * 2 + 0] = (float)i1;
        idx_out[tok * 2 + 1] = (float)i2;
    }
}

// ---- Phase 3: exact rescue of flagged tokens, band candidates only ----
__global__ __launch_bounds__(256, 2)
void moirai_rescue_kernel(const float* __restrict__ x,
                          const float* __restrict__ W,
                          const float* __restrict__ b,
                          float* __restrict__ out)
{
    __shared__ float s_log[E_DIM];
    __shared__ int   s_cand[E_DIM];
    __shared__ int   s_n;
    __shared__ float s_part[8];
    __shared__ float s_exact[E_DIM];

    const int tid = threadIdx.x;
    const int cnt = min(g_cnt, NTOK);

    for (int i = blockIdx.x; i < cnt; i += gridDim.x) {
        const int tok = g_flags[i];

        if (tid < E_DIM)
            s_log[tid] = g_scratch[(size_t)tok * E_DIM + tid]
                       + g_scratch[(size_t)(NTOK + tok) * E_DIM + tid] + b[tid];
        __syncthreads();

        if (tid == 0) {
            float v1 = -CUDART_INF_F, v2 = -CUDART_INF_F;
            for (int e = 0; e < E_DIM; e++) {
                float v = s_log[e];
                if (v > v1)      { v2 = v1; v1 = v; }
                else if (v > v2) { v2 = v; }
            }
            float band = v2 - TH_BAND;
            int n = 0;
            for (int e = 0; e < E_DIM; e++)
                if (s_log[e] >= band) s_cand[n++] = e;
            s_n = n;
        }
        __syncthreads();
        const int n = s_n;

        for (int c = 0; c < n; c++) {
            const int e = s_cand[c];
            const float* xr = x + (size_t)tok * D_DIM + tid * 16;
            const float* wr = W + (size_t)e * D_DIM + tid * 16;
            float s = 0.0f;
#pragma unroll
            for (int k = 0; k < 16; k += 4) {
                float4 a  = *reinterpret_cast<const float4*>(xr + k);
                float4 ww = *reinterpret_cast<const float4*>(wr + k);
                s += a.x * ww.x + a.y * ww.y + a.z * ww.z + a.w * ww.w;
            }
#pragma unroll
            for (int m = 16; m; m >>= 1) s += __shfl_xor_sync(0xFFFFFFFFu, s, m);
            if ((tid & 31) == 0) s_part[tid >> 5] = s;
            __syncthreads();
            if (tid == 0) {
                float tot = 0.0f;
#pragma unroll
                for (int ww = 0; ww < 8; ww++) tot += s_part[ww];
                s_exact[c] = tot + b[e];
            }
            __syncthreads();
        }

        if (tid == 0) {
            float v1 = -CUDART_INF_F, v2 = -CUDART_INF_F;
            int i1 = 0, i2 = 0;
            for (int c = 0; c < n; c++) {
                int e = s_cand[c];
                float v = s_exact[c];
                if (v > v1)      { v2 = v1; i2 = i1; v1 = v; i1 = e; }
                else if (v > v2) { v2 = v; i2 = e; }
            }
            float ex  = expf(v2 - v1);
            float inv = 1.0f / (1.0f + ex);
            out[tok * 2 + 0] = inv;
            out[tok * 2 + 1] = ex * inv;
            float* idx_out = out + (size_t)NTOK * 2;
            idx_out[tok * 2 + 0] = (float)i1;
            idx_out[tok * 2 + 1] = (float)i2;
        }
        __syncthreads();
    }
}

extern "C" void kernel_launch(void* const* d_in, const int* in_sizes, int n_in,
                              void* d_out, int out_size)
{
    const float* x = (const float*)d_in[0];
    const float* W = (const float*)d_in[1];
    const float* b = (const float*)d_in[2];
    float* out = (float*)d_out;

    cudaFuncSetAttribute(moirai_gemm_kernel,
                         cudaFuncAttributeMaxDynamicSharedMemorySize, SMEM_ALLOC);
    moirai_gemm_kernel<<<128, 512, SMEM_ALLOC>>>(x, W);
    moirai_topk_kernel<<<(NTOK * 2) / 256, 256>>>(b, out);
    moirai_rescue_kernel<<<128, 256>>>(x, W, b, out);
}

// round 17
// speedup vs baseline: 1.1028x; 1.0655x over previous
#include <cuda_runtime.h>
#include <cuda_fp16.h>
#include <math_constants.h>
#include <cstdint>

// FixedMoiraiGating: logits = x @ W^T + b ; top-2 ; softmax over the 2 vals.
// x: [8192, 4096] f32, W: [64, 4096] f32, b: [64] f32
// out f32[32768]: [0,16384) = probs; [16384,32768) = indices as float.
//
// R17 = R16 resubmit (infra flake): 2-term GEMM (logits' = (xh+xl) @ wh^T),
// A-ring depth 4 AND pipelined converts (load g+4, convert g+1 during g).
// Phase 2: 4 lanes/token top-3 + flag gap < 1e-3 (128 CTAs). Phase 3: banded
// exact rescue of flagged tokens.

#define D_DIM  4096
#define E_DIM  64
#define BM     128
#define KHALF  2048
#define KGRP   1024
#define KC     64
#define NSG    (KGRP / KC)    // 16 stages/group
#define NKG    (KGRP / 16)    // 64 ksteps/group
#define NTOK   8192
#define TH_FLAG 1e-3f
#define TH_BAND 1.5e-3f

#define BH(g, d)   ((g) * 16384 + (d) * 8192)
#define SMEM_ALLOC (32768 + 1024)

__device__ float g_scratch[2 * NTOK * E_DIM];
__device__ int   g_cnt;
__device__ int   g_flags[NTOK];

#define MMA16816(c, a0, a1, a2, a3, b0, b1) \
    asm volatile("mma.sync.aligned.m16n8k16.row.col.f32.f16.f16.f32 " \
                 "{%0,%1,%2,%3}, {%4,%5,%6,%7}, {%8,%9}, {%0,%1,%2,%3};" \
                 : "+f"((c)[0]), "+f"((c)[1]), "+f"((c)[2]), "+f"((c)[3]) \
                 : "r"(a0), "r"(a1), "r"(a2), "r"(a3), "r"(b0), "r"(b1))

#define LDSM_X4(r0, r1, r2, r3, addr) \
    asm volatile("ldmatrix.sync.aligned.m8n8.x4.shared.b16 {%0,%1,%2,%3}, [%4];" \
                 : "=r"(r0), "=r"(r1), "=r"(r2), "=r"(r3) : "r"(addr))

static __device__ __forceinline__ uint32_t smem_u32(const void* p) {
    uint32_t a;
    asm("{ .reg .u64 t; cvta.to.shared.u64 t, %1; cvt.u32.u64 %0, t; }"
        : "=r"(a) : "l"(p));
    return a;
}

static __device__ __forceinline__ uint32_t h2u(__half2 h) {
    return *reinterpret_cast<uint32_t*>(&h);
}

static __device__ __forceinline__ void split2(float2 v, uint32_t& hi, uint32_t& lo) {
    __half2 h = __floats2half2_rn(v.x, v.y);
    float2 bk = __half22float2(h);
    __half2 l = __floats2half2_rn(v.x - bk.x, v.y - bk.y);
    hi = h2u(h);
    lo = h2u(l);
}

static __device__ __forceinline__ uint32_t bswz(int n, uint32_t kbyte) {
    return (uint32_t)(n * 128) + (kbyte ^ (uint32_t)((n & 7) << 4));
}

// ---- Phase 1: 2-term GEMM, A-ring-4 + pipelined converts ----
__global__ __launch_bounds__(512, 1)
void moirai_gemm_kernel(const float* __restrict__ x,
                        const float* __restrict__ W)
{
    extern __shared__ uint8_t smem_raw[];
    const uint32_t base = (smem_u32(smem_raw) + 1023u) & ~1023u;

    if (blockIdx.x == 0 && threadIdx.x == 0) g_cnt = 0;

    const int t    = threadIdx.x;
    const int w    = t >> 5;
    const int lane = t & 31;
    const int gi   = w >> 3;
    const int wg   = w & 7;
    const int tg   = t & 255;
    const int tq   = lane >> 2;
    const int tr   = lane & 3;
    const int mt   = blockIdx.x & 63;
    const int kh   = blockIdx.x >> 6;
    const int tok0 = mt * BM;
    const int kbg  = kh * KHALF + gi * KGRP;

    const uint32_t bh0 = base + BH(gi, 0);
    const uint32_t bh1 = base + BH(gi, 1);

    const int t7 = lane & 7;
    const int j  = lane >> 3;
    const int jp = j & 1;
    const int jh = j >> 1;
    const uint32_t lanePart = (uint32_t)(jh * 1024 + t7 * 128);
    const uint32_t xorTerm  = (uint32_t)(t7 << 4);

    float acc[8][4];
#pragma unroll
    for (int nt = 0; nt < 8; nt++)
#pragma unroll
        for (int c = 0; c < 4; c++) acc[nt][c] = 0.0f;

    const int rA = tok0 + wg * 16 + tq;

    float2 af[4][4];                 // A f32 ring, depth 4 ksteps
#define LOAD_A(slot, g) do {                                            \
        int kc_ = kbg + (g) * 16 + 2 * tr;                              \
        const float* p0_ = x + (size_t)rA * D_DIM + kc_;                \
        const float* p1_ = x + (size_t)(rA + 8) * D_DIM + kc_;          \
        af[slot][0] = *reinterpret_cast<const float2*>(p0_);            \
        af[slot][1] = *reinterpret_cast<const float2*>(p0_ + 8);        \
        af[slot][2] = *reinterpret_cast<const float2*>(p1_);            \
        af[slot][3] = *reinterpret_cast<const float2*>(p1_ + 8);        \
    } while (0)

    float4 bf4[4];
    int   brow[4], bc4[4];
#pragma unroll
    for (int i = 0; i < 4; i++) {
        int p = tg + i * 256;
        brow[i] = p >> 4;
        bc4[i]  = p & 15;
    }

#pragma unroll
    for (int i = 0; i < 4; i++)
        bf4[i] = *reinterpret_cast<const float4*>(
            W + (size_t)brow[i] * D_DIM + kbg + bc4[i] * 4);
    LOAD_A(0, 0);
    LOAD_A(1, 1);
    LOAD_A(2, 2);
    LOAD_A(3, 3);
#pragma unroll
    for (int i = 0; i < 4; i++) {
        __half2 h0 = __floats2half2_rn(bf4[i].x, bf4[i].y);
        __half2 h1 = __floats2half2_rn(bf4[i].z, bf4[i].w);
        uint32_t off = bswz(brow[i], (uint32_t)(bc4[i] * 8));
        asm volatile("st.shared.v2.b32 [%0], {%1,%2};" :: "r"(bh0 + off),
                     "r"(h2u(h0)), "r"(h2u(h1)) : "memory");
    }

    // pipelined converted-A sets (parity = global kstep & 1), single-set B frags
    uint32_t bhf[8][2];
    uint32_t ah2[2][4], al2[2][4];

#define CVT_A(set, g) do {                                                      \
        _Pragma("unroll")                                                       \
        for (int jj_ = 0; jj_ < 4; jj_++)                                       \
            split2(af[(g) & 3][jj_], ah2[set][jj_], al2[set][jj_]);             \
    } while (0)

    CVT_A(0, 0);          // prime kstep 0 (af only; legal before barrier)
    __syncthreads();

    for (int stage = 0; stage < NSG; stage++) {
        const uint32_t curh = (stage & 1) ? bh1 : bh0;
        const uint32_t nxth = (stage & 1) ? bh0 : bh1;
        const int g0 = stage * 4;

        if (stage + 1 < NSG) {
            const int kbs = kbg + (stage + 1) * KC;
#pragma unroll
            for (int i = 0; i < 4; i++)
                bf4[i] = *reinterpret_cast<const float4*>(
                    W + (size_t)brow[i] * D_DIM + kbs + bc4[i] * 4);
        }

#pragma unroll
        for (int ks = 0; ks < 4; ks++) {
            const int g = g0 + ks;
            const int set = g & 1;

            // B fragments for this kstep
            const uint32_t kpart = ((uint32_t)(ks << 5) | (uint32_t)(jp << 4)) ^ xorTerm;
#pragma unroll
            for (int q = 0; q < 8; q += 2) {
                uint32_t a_ = curh + (uint32_t)(q * 1024) + lanePart + kpart;
                LDSM_X4(bhf[q][0], bhf[q][1], bhf[q + 1][0], bhf[q + 1][1], a_);
            }

            // convert next kstep's A (read af[g+1 & 3], loaded >=3 ksteps ago)
            if (g + 1 < NKG) CVT_A(set ^ 1, g + 1);
            // refill ring: slot g&3 was consumed by the convert at kstep g-1
            if (g + 4 < NKG) LOAD_A(g & 3, g + 4);

#pragma unroll
            for (int nt = 0; nt < 8; nt++) {
                MMA16816(acc[nt], ah2[set][0], ah2[set][2], ah2[set][1], ah2[set][3],
                         bhf[nt][0], bhf[nt][1]);
                MMA16816(acc[nt], al2[set][0], al2[set][2], al2[set][1], al2[set][3],
                         bhf[nt][0], bhf[nt][1]);
            }
        }

        if (stage + 1 < NSG) {
#pragma unroll
            for (int i = 0; i < 4; i++) {
                __half2 h0 = __floats2half2_rn(bf4[i].x, bf4[i].y);
                __half2 h1 = __floats2half2_rn(bf4[i].z, bf4[i].w);
                uint32_t off = bswz(brow[i], (uint32_t)(bc4[i] * 8));
                asm volatile("st.shared.v2.b32 [%0], {%1,%2};" :: "r"(nxth + off),
                             "r"(h2u(h0)), "r"(h2u(h1)) : "memory");
            }
        }
        __syncthreads();
    }

    // combine the two K-groups
    if (gi == 1) {
        uint32_t dst = base + (uint32_t)(wg * 4096 + lane * 128);
#pragma unroll
        for (int nt = 0; nt < 8; nt++) {
            asm volatile("st.shared.v4.b32 [%0], {%1,%2,%3,%4};" ::
                         "r"(dst + nt * 16),
                         "f"(acc[nt][0]), "f"(acc[nt][1]),
                         "f"(acc[nt][2]), "f"(acc[nt][3]) : "memory");
        }
    }
    __syncthreads();

    if (gi == 0) {
        uint32_t src = base + (uint32_t)(wg * 4096 + lane * 128);
#pragma unroll
        for (int nt = 0; nt < 8; nt++) {
            float r0, r1, r2, r3;
            asm volatile("ld.shared.v4.b32 {%0,%1,%2,%3}, [%4];"
                         : "=f"(r0), "=f"(r1), "=f"(r2), "=f"(r3)
                         : "r"(src + nt * 16));
            acc[nt][0] += r0; acc[nt][1] += r1;
            acc[nt][2] += r2; acc[nt][3] += r3;
        }
        float* sbase = g_scratch + (size_t)kh * NTOK * E_DIM;
#pragma unroll
        for (int nt = 0; nt < 8; nt++) {
            int col = nt * 8 + 2 * tr;
            *reinterpret_cast<float2*>(sbase + (size_t)rA * E_DIM + col) =
                make_float2(acc[nt][0], acc[nt][1]);
            *reinterpret_cast<float2*>(sbase + (size_t)(rA + 8) * E_DIM + col) =
                make_float2(acc[nt][2], acc[nt][3]);
        }
    }
}

// ---- Phase 2: 4 lanes/token: combine + bias, top-3, flag, provisional out ----
__global__ __launch_bounds__(256, 4)
void moirai_topk_kernel(const float* __restrict__ b,
                        float* __restrict__ out)
{
    const int gid  = blockIdx.x * 256 + threadIdx.x;
    const int tok  = gid >> 2;
    const int r    = gid & 3;          // experts [r*16, r*16+16)

    const float* r0 = g_scratch + (size_t)tok * E_DIM + r * 16;
    const float* r1 = g_scratch + ((size_t)NTOK + tok) * E_DIM + r * 16;
    const float* bb = b + r * 16;

    float v1 = -CUDART_INF_F, v2 = -CUDART_INF_F, v3 = -CUDART_INF_F;
    int i1 = 0, i2 = 0;
#pragma unroll
    for (int g = 0; g < 4; g++) {
        float4 a  = *reinterpret_cast<const float4*>(r0 + g * 4);
        float4 c  = *reinterpret_cast<const float4*>(r1 + g * 4);
        float4 bv = *reinterpret_cast<const float4*>(bb + g * 4);
        float v[4] = {a.x + c.x + bv.x, a.y + c.y + bv.y,
                      a.z + c.z + bv.z, a.w + c.w + bv.w};
#pragma unroll
        for (int jj = 0; jj < 4; jj++) {
            int e = r * 16 + g * 4 + jj;
            if (v[jj] > v1)      { v3 = v2; v2 = v1; i2 = i1; v1 = v[jj]; i1 = e; }
            else if (v[jj] > v2) { v3 = v2; v2 = v[jj]; i2 = e; }
            else if (v[jj] > v3) { v3 = v[jj]; }
        }
    }

#pragma unroll
    for (int m = 1; m <= 2; m <<= 1) {
        float V1 = __shfl_xor_sync(0xFFFFFFFFu, v1, m);
        float V2 = __shfl_xor_sync(0xFFFFFFFFu, v2, m);
        float V3 = __shfl_xor_sync(0xFFFFFFFFu, v3, m);
        int   I1 = __shfl_xor_sync(0xFFFFFFFFu, i1, m);
        int   I2 = __shfl_xor_sync(0xFFFFFFFFu, i2, m);

        if (V1 > v1 || (V1 == v1 && I1 < i1)) {
            float tv; int ti;
            tv = v1; v1 = V1; V1 = tv;  ti = i1; i1 = I1; I1 = ti;
            tv = v2; v2 = V2; V2 = tv;  ti = i2; i2 = I2; I2 = ti;
            tv = v3; v3 = V3; V3 = tv;
        }
        if (V1 > v2 || (V1 == v2 && I1 < i2)) {
            v3 = fmaxf(v2, V2);
            v2 = V1; i2 = I1;
        } else {
            v3 = fmaxf(v3, V1);
        }
    }

    if (r == 0) {
        if ((v1 - v2 < TH_FLAG) || (v2 - v3 < TH_FLAG)) {
            int idx = atomicAdd(&g_cnt, 1);
            if (idx < NTOK) g_flags[idx] = tok;
        }
        float ex  = expf(v2 - v1);
        float inv = 1.0f / (1.0f + ex);
        out[tok * 2 + 0] = inv;
        out[tok * 2 + 1] = ex * inv;
        float* idx_out = out + (size_t)NTOK * 2;
        idx_out[tok * 2 + 0] = (float)i1;
        idx_out[tok * 2 + 1] = (float)i2;
    }
}

// ---- Phase 3: exact rescue of flagged tokens, band candidates only ----
__global__ __launch_bounds__(256, 2)
void moirai_rescue_kernel(const float* __restrict__ x,
                          const float* __restrict__ W,
                          const float* __restrict__ b,
                          float* __restrict__ out)
{
    __shared__ float s_log[E_DIM];
    __shared__ int   s_cand[E_DIM];
    __shared__ int   s_n;
    __shared__ float s_part[8];
    __shared__ float s_exact[E_DIM];

    const int tid = threadIdx.x;
    const int cnt = min(g_cnt, NTOK);

    for (int i = blockIdx.x; i < cnt; i += gridDim.x) {
        const int tok = g_flags[i];

        if (tid < E_DIM)
            s_log[tid] = g_scratch[(size_t)tok * E_DIM + tid]
                       + g_scratch[(size_t)(NTOK + tok) * E_DIM + tid] + b[tid];
        __syncthreads();

        if (tid == 0) {
            float v1 = -CUDART_INF_F, v2 = -CUDART_INF_F;
            for (int e = 0; e < E_DIM; e++) {
                float v = s_log[e];
                if (v > v1)      { v2 = v1; v1 = v; }
                else if (v > v2) { v2 = v; }
            }
            float band = v2 - TH_BAND;
            int n = 0;
            for (int e = 0; e < E_DIM; e++)
                if (s_log[e] >= band) s_cand[n++] = e;
            s_n = n;
        }
        __syncthreads();
        const int n = s_n;

        for (int c = 0; c < n; c++) {
            const int e = s_cand[c];
            const float* xr = x + (size_t)tok * D_DIM + tid * 16;
            const float* wr = W + (size_t)e * D_DIM + tid * 16;
            float s = 0.0f;
#pragma unroll
            for (int k = 0; k < 16; k += 4) {
                float4 a  = *reinterpret_cast<const float4*>(xr + k);
                float4 ww = *reinterpret_cast<const float4*>(wr + k);
                s += a.x * ww.x + a.y * ww.y + a.z * ww.z + a.w * ww.w;
            }
#pragma unroll
            for (int m = 16; m; m >>= 1) s += __shfl_xor_sync(0xFFFFFFFFu, s, m);
            if ((tid & 31) == 0) s_part[tid >> 5] = s;
            __syncthreads();
            if (tid == 0) {
                float tot = 0.0f;
#pragma unroll
                for (int ww = 0; ww < 8; ww++) tot += s_part[ww];
                s_exact[c] = tot + b[e];
            }
            __syncthreads();
        }

        if (tid == 0) {
            float v1 = -CUDART_INF_F, v2 = -CUDART_INF_F;
            int i1 = 0, i2 = 0;
            for (int c = 0; c < n; c++) {
                int e = s_cand[c];
                float v = s_exact[c];
                if (v > v1)      { v2 = v1; i2 = i1; v1 = v; i1 = e; }
                else if (v > v2) { v2 = v; i2 = e; }
            }
            float ex  = expf(v2 - v1);
            float inv = 1.0f / (1.0f + ex);
            out[tok * 2 + 0] = inv;
            out[tok * 2 + 1] = ex * inv;
            float* idx_out = out + (size_t)NTOK * 2;
            idx_out[tok * 2 + 0] = (float)i1;
            idx_out[tok * 2 + 1] = (float)i2;
        }
        __syncthreads();
    }
}

extern "C" void kernel_launch(void* const* d_in, const int* in_sizes, int n_in,
                              void* d_out, int out_size)
{
    const float* x = (const float*)d_in[0];
    const float* W = (const float*)d_in[1];
    const float* b = (const float*)d_in[2];
    float* out = (float*)d_out;

    cudaFuncSetAttribute(moirai_gemm_kernel,
                         cudaFuncAttributeMaxDynamicSharedMemorySize, SMEM_ALLOC);
    moirai_gemm_kernel<<<128, 512, SMEM_ALLOC>>>(x, W);
    moirai_topk_kernel<<<(NTOK * 4) / 256, 256>>>(b, out);
    moirai_rescue_kernel<<<128, 256>>>(x, W, b, out);
}